// round 13
// baseline (speedup 1.0000x reference)
#include <cuda_runtime.h>
#include <cuda_fp16.h>
#include <cstdint>
#include <cstddef>

// Problem constants (fixed by the reference)
#define BB 64
#define TT 2048
#define DIN 128
#define HH 512
#define DOUT 128
#define MM (BB * TT)   // 131072

// Scratch buffers (allocation-guard-safe __device__ globals)
__device__ __align__(256) float  g_proj[(size_t)MM * HH];   // fp32 proj
__device__ __align__(256) __half g_act[(size_t)MM * HH];    // fp16 activations (scaled)
__device__ __align__(256) __half g_x16[(size_t)MM * DIN];   // fp16 x
__device__ __align__(256) __half g_w0[HH * DIN];
__device__ __align__(256) __half g_w1[HH * HH];
__device__ __align__(256) __half g_fw[DOUT * HH];

// ---------------------------------------------------------------------------
// PTX helpers
// ---------------------------------------------------------------------------
__device__ __forceinline__ uint32_t smem_u32(const void* p) {
    uint32_t a;
    asm("{ .reg .u64 t; cvta.to.shared.u64 t, %1; cvt.u32.u64 %0, t; }"
        : "=r"(a) : "l"(p));
    return a;
}

__device__ __forceinline__ void cp_async16(uint32_t dst, const void* src) {
    asm volatile("cp.async.cg.shared.global [%0], [%1], 16;"
                 :: "r"(dst), "l"(src));
}
#define CP_COMMIT() asm volatile("cp.async.commit_group;" ::: "memory")
#define CP_WAIT3()  asm volatile("cp.async.wait_group 3;" ::: "memory")

// mma m16n8k16 fp16 inputs, fp32 accumulate (in place)
__device__ __forceinline__ void mma_f16(float* c,
                                        uint32_t a0, uint32_t a1,
                                        uint32_t a2, uint32_t a3,
                                        uint32_t b0, uint32_t b1) {
    asm volatile(
        "mma.sync.aligned.m16n8k16.row.col.f32.f16.f16.f32 "
        "{%0,%1,%2,%3}, {%4,%5,%6,%7}, {%8,%9}, {%0,%1,%2,%3};"
        : "+f"(c[0]), "+f"(c[1]), "+f"(c[2]), "+f"(c[3])
        : "r"(a0), "r"(a1), "r"(a2), "r"(a3), "r"(b0), "r"(b1));
}

// ldmatrix x4 (b16): four 8x8 tiles, one per 8-lane group
__device__ __forceinline__ void ldsm_x4(uint32_t& r0, uint32_t& r1,
                                        uint32_t& r2, uint32_t& r3,
                                        uint32_t addr) {
    asm volatile("ldmatrix.sync.aligned.m8n8.x4.shared.b16 {%0,%1,%2,%3}, [%4];"
                 : "=r"(r0), "=r"(r1), "=r"(r2), "=r"(r3) : "r"(addr));
}

// ---------------------------------------------------------------------------
// fp16 GEMM (NT): C[M,N] = out_scale*(A[M,K] * B[N,K]^T) + (b1 + b2)
// Block 128x128, BK=32, 8 warps (2x4), warp tile 64x32.
// cp.async 5-stage pipeline (wait_group 3: stage kt landed, three in flight);
// ldmatrix fragment loads.
// smem rows: 32 fp16 = 64B data + 16B pad = 80B (conflict-free LDSM phases).
// Requires M%128==0, N%128==0, K%32==0, K/32 >= 4.
// ---------------------------------------------------------------------------
#define ROWB   80
#define TILE_B (128 * ROWB)        // 10240
#define STAGE_B (2 * TILE_B)       // 20480 (A, B)
#define NSTAGE 5
#define SMEM_GEMM (512 + NSTAGE * STAGE_B)   // 102912

__global__ __launch_bounds__(256, 2)
void gemm_f16(const __half* __restrict__ A,
              const __half* __restrict__ Bw,
              const float* __restrict__ bias1,
              const float* __restrict__ bias2,
              float* __restrict__ C,
              int M, int N, int K, float out_scale)
{
    extern __shared__ char smem[];
    float* biasS = (float*)smem;
    char* tiles = smem + 512;
    const uint32_t tilesU = smem_u32(tiles);

    const int tid  = threadIdx.x;
    const int wid  = tid >> 5;
    const int lane = tid & 31;
    const int bm = blockIdx.y * 128;
    const int bn = blockIdx.x * 128;

    const int wm = (wid >> 2) * 64;
    const int wn = (wid & 3) * 32;
    const int g0 = lane >> 2;

    if (tid < 128) {
        float bv = bias1[bn + tid];
        if (bias2) bv += bias2[bn + tid];
        biasS[tid] = bv;
    }

    // cp.async mapping: thread -> rows (tid>>2) and (tid>>2)+64, col (tid&3)*16B
    const int crow = tid >> 2;
    const size_t rstride = (size_t)K * 2;   // bytes per gmem row
    const int ccol = (tid & 3) * 16;

    const char* Ag = (const char*)A  + (size_t)(bm + crow) * rstride + ccol;
    const char* Bg = (const char*)Bw + (size_t)(bn + crow) * rstride + ccol;
    const size_t r64 = 64 * rstride;

    const uint32_t sbase = tilesU + crow * ROWB + (tid & 3) * 16;

    // ldmatrix per-lane base addresses (within stage 0)
    const uint32_t aAddr = tilesU + (wm + (lane & 15)) * ROWB + (lane >> 4) * 16;
    const uint32_t bAddr = tilesU + TILE_B
                         + (wn + (lane >> 4) * 8 + (lane & 7)) * ROWB
                         + ((lane >> 3) & 1) * 16;

    float acc[4][4][4];
    #pragma unroll
    for (int mt = 0; mt < 4; mt++)
        #pragma unroll
        for (int nt = 0; nt < 4; nt++)
            #pragma unroll
            for (int j = 0; j < 4; j++)
                acc[mt][nt][j] = 0.0f;

    const int NK = K >> 5;

    auto load_stage = [&](int s, int kt) {
        uint32_t d = sbase + s * STAGE_B;
        size_t go = (size_t)kt * 64;     // 32 fp16 = 64 bytes
        cp_async16(d,                 Ag + go);
        cp_async16(d + 64 * ROWB,     Ag + go + r64);
        cp_async16(d + TILE_B,            Bg + go);
        cp_async16(d + TILE_B + 64 * ROWB, Bg + go + r64);
    };

    load_stage(0, 0); CP_COMMIT();
    load_stage(1, 1); CP_COMMIT();
    load_stage(2, 2); CP_COMMIT();
    load_stage(3, 3); CP_COMMIT();

    for (int kt = 0; kt < NK; kt++) {
        CP_WAIT3();          // stage kt landed (kt+1..kt+3 may be in flight)
        __syncthreads();     // prev iter's MMAs done -> buffer (kt+4)%5 free

        if (kt + 4 < NK) load_stage((kt + 4) % 5, kt + 4);
        CP_COMMIT();         // unconditional: keeps group counting aligned

        const uint32_t stU = (kt % 5) * STAGE_B;

        #pragma unroll
        for (int ko = 0; ko < 2; ko++) {
            const uint32_t kb = stU + ko * 32;

            uint32_t Af[4][4];
            #pragma unroll
            for (int mt = 0; mt < 4; mt++)
                ldsm_x4(Af[mt][0], Af[mt][1], Af[mt][2], Af[mt][3],
                        aAddr + kb + mt * (16 * ROWB));

            uint32_t Bf[2][4];
            #pragma unroll
            for (int np = 0; np < 2; np++)
                ldsm_x4(Bf[np][0], Bf[np][1], Bf[np][2], Bf[np][3],
                        bAddr + kb + np * (16 * ROWB));

            #pragma unroll
            for (int mt = 0; mt < 4; mt++)
                #pragma unroll
                for (int nt = 0; nt < 4; nt++) {
                    const int np = nt >> 1, pr = (nt & 1) * 2;
                    mma_f16(acc[mt][nt],
                            Af[mt][0], Af[mt][1], Af[mt][2], Af[mt][3],
                            Bf[np][pr], Bf[np][pr + 1]);
                }
        }
    }

    // Epilogue: scale + bias + float2 stores (full 32B sectors)
    const int c0 = (lane & 3) * 2;
    #pragma unroll
    for (int mt = 0; mt < 4; mt++) {
        #pragma unroll
        for (int nt = 0; nt < 4; nt++) {
            int colL = wn + nt * 8 + c0;
            int col  = bn + colL;
            float b0v = biasS[colL];
            float b1v = biasS[colL + 1];
            int row0 = bm + wm + mt * 16 + g0;
            float2 v0 = make_float2(fmaf(acc[mt][nt][0], out_scale, b0v),
                                    fmaf(acc[mt][nt][1], out_scale, b1v));
            float2 v1 = make_float2(fmaf(acc[mt][nt][2], out_scale, b0v),
                                    fmaf(acc[mt][nt][3], out_scale, b1v));
            *(float2*)(C + (size_t)row0 * N + col)       = v0;
            *(float2*)(C + (size_t)(row0 + 8) * N + col) = v1;
        }
    }
}

// ---------------------------------------------------------------------------
// IndRNN scan, fp16 output with power-of-2 down-scaling (range protection):
//   O[b,t,h] = fp16( relu(P[b,t,h] + u[h]*h_prev) * store_scale )
// U=32 with next-block prefetch (at the mixed-stream DRAM ceiling).
// ---------------------------------------------------------------------------
__global__ void scan_relu_f16(const float* __restrict__ P,
                              const float* __restrict__ u,
                              __half* __restrict__ O,
                              float store_scale)
{
    int idx = blockIdx.x * blockDim.x + threadIdx.x;
    if (idx >= BB * HH) return;
    int b = idx / HH;
    int h = idx - b * HH;
    float uu = u[h];
    float hv = 0.0f;
    const float* p = P + (size_t)b * TT * HH + h;
    __half* o = O + (size_t)b * TT * HH + h;

    constexpr int U = 32;
    float x[U];
    #pragma unroll
    for (int i = 0; i < U; i++) x[i] = p[(size_t)i * HH];

    #pragma unroll 1
    for (int t = 0; t < TT; t += U) {
        float y[U];
        bool more = (t + U) < TT;
        const float* pn = p + (size_t)U * HH;
        if (more) {
            #pragma unroll
            for (int i = 0; i < U; i++) y[i] = pn[(size_t)i * HH];
        }
        #pragma unroll
        for (int i = 0; i < U; i++) {
            hv = fmaxf(fmaf(uu, hv, x[i]), 0.0f);
            o[(size_t)i * HH] = __float2half_rn(hv * store_scale);
        }
        #pragma unroll
        for (int i = 0; i < U; i++) x[i] = y[i];
        p = pn;
        o += (size_t)U * HH;
    }
}

// ---------------------------------------------------------------------------
// Converters
// ---------------------------------------------------------------------------
__global__ void f32_to_f16(const float* __restrict__ in,
                           __half* __restrict__ out, int n)
{
    int i = (blockIdx.x * blockDim.x + threadIdx.x) * 4;
    if (i < n) {
        float4 v = *(const float4*)(in + i);
        __half2 h0 = __floats2half2_rn(v.x, v.y);
        __half2 h1 = __floats2half2_rn(v.z, v.w);
        *(uint2*)(out + i) = make_uint2(*(uint32_t*)&h0, *(uint32_t*)&h1);
    }
}

__global__ void convert_weights(const float* __restrict__ W0,
                                const float* __restrict__ W1,
                                const float* __restrict__ FW,
                                __half* __restrict__ w0,
                                __half* __restrict__ w1,
                                __half* __restrict__ fw)
{
    constexpr int n0 = HH * DIN;           // 65536
    constexpr int n1 = HH * HH;            // 262144
    constexpr int n2 = DOUT * HH;          // 65536
    int i = (blockIdx.x * blockDim.x + threadIdx.x) * 4;
    const float* src;
    __half* dst;
    int j;
    if (i < n0)           { src = W0; dst = w0; j = i; }
    else if (i < n0 + n1) { src = W1; dst = w1; j = i - n0; }
    else if (i < n0 + n1 + n2) { src = FW; dst = fw; j = i - n0 - n1; }
    else return;
    float4 v = *(const float4*)(src + j);
    __half2 h0 = __floats2half2_rn(v.x, v.y);
    __half2 h1 = __floats2half2_rn(v.z, v.w);
    *(uint2*)(dst + j) = make_uint2(*(uint32_t*)&h0, *(uint32_t*)&h1);
}

extern "C" void kernel_launch(void* const* d_in, const int* in_sizes, int n_in,
                              void* d_out, int out_size)
{
    const float* x    = (const float*)d_in[0];
    const float* W0   = (const float*)d_in[1];
    const float* bl0  = (const float*)d_in[2];
    const float* u0   = (const float*)d_in[3];
    const float* bb0  = (const float*)d_in[4];
    const float* W1   = (const float*)d_in[5];
    const float* bl1  = (const float*)d_in[6];
    const float* u1   = (const float*)d_in[7];
    const float* bb1  = (const float*)d_in[8];
    const float* fcW  = (const float*)d_in[9];
    const float* fcb  = (const float*)d_in[10];
    float* out = (float*)d_out;

    float  *proj;
    __half *act, *x16, *w0, *w1, *fw;
    cudaGetSymbolAddress((void**)&proj, g_proj);
    cudaGetSymbolAddress((void**)&act,  g_act);
    cudaGetSymbolAddress((void**)&x16,  g_x16);
    cudaGetSymbolAddress((void**)&w0,   g_w0);
    cudaGetSymbolAddress((void**)&w1,   g_w1);
    cudaGetSymbolAddress((void**)&fw,   g_fw);

    cudaFuncSetAttribute(gemm_f16,
                         cudaFuncAttributeMaxDynamicSharedMemorySize,
                         SMEM_GEMM);

    // All weights -> fp16 in one launch
    {
        int total = HH * DIN + HH * HH + DOUT * HH;   // 393216
        convert_weights<<<(total / 4 + 255) / 256, 256>>>(W0, W1, fcW,
                                                          w0, w1, fw);
    }
    // x -> fp16
    {
        int n = MM * DIN;
        f32_to_f16<<<(n / 4 + 255) / 256, 256>>>(x, x16, n);
    }

    // GEMM0: proj = x16 @ W0^T + bl0 + bb0   [M, H], K=128
    {
        dim3 grid(HH / 128, MM / 128);
        gemm_f16<<<grid, 256, SMEM_GEMM>>>(x16, w0, bl0, bb0, proj,
                                           MM, HH, DIN, 1.0f);
    }
    // scan0 -> act = h1 * 2^-4
    scan_relu_f16<<<(BB * HH) / 128, 128>>>(proj, u0, act, 0.0625f);

    // GEMM1: proj = (h1*2^-4) @ W1^T * 16 + bl1 + bb1  [M, H], K=512
    {
        dim3 grid(HH / 128, MM / 128);
        gemm_f16<<<grid, 256, SMEM_GEMM>>>(act, w1, bl1, bb1, proj,
                                           MM, HH, HH, 16.0f);
    }
    // scan1 -> act = h2 * 2^-8
    scan_relu_f16<<<(BB * HH) / 128, 128>>>(proj, u1, act, 0.00390625f);

    // GEMM2: out = (h2*2^-8) @ fcW^T * 256 + fcb  [M, Dout], K=512
    {
        dim3 grid(DOUT / 128, MM / 128);
        gemm_f16<<<grid, 256, SMEM_GEMM>>>(act, fw, fcb, nullptr, out,
                                           MM, DOUT, HH, 256.0f);
    }
}

// round 14
// speedup vs baseline: 1.1061x; 1.1061x over previous
#include <cuda_runtime.h>
#include <cuda_fp16.h>
#include <cstdint>
#include <cstddef>

// Problem constants (fixed by the reference)
#define BB 64
#define TT 2048
#define DIN 128
#define HH 512
#define DOUT 128
#define MM (BB * TT)   // 131072

// Scratch buffers (allocation-guard-safe __device__ globals)
__device__ __align__(256) __half g_proj[(size_t)MM * HH];   // fp16 proj (scaled)
__device__ __align__(256) __half g_act[(size_t)MM * HH];    // fp16 activations (scaled)
__device__ __align__(256) __half g_x16[(size_t)MM * DIN];   // fp16 x
__device__ __align__(256) __half g_w0[HH * DIN];
__device__ __align__(256) __half g_w1[HH * HH];
__device__ __align__(256) __half g_fw[DOUT * HH];

// ---------------------------------------------------------------------------
// PTX helpers
// ---------------------------------------------------------------------------
__device__ __forceinline__ uint32_t smem_u32(const void* p) {
    uint32_t a;
    asm("{ .reg .u64 t; cvta.to.shared.u64 t, %1; cvt.u32.u64 %0, t; }"
        : "=r"(a) : "l"(p));
    return a;
}

__device__ __forceinline__ void cp_async16(uint32_t dst, const void* src) {
    asm volatile("cp.async.cg.shared.global [%0], [%1], 16;"
                 :: "r"(dst), "l"(src));
}
#define CP_COMMIT() asm volatile("cp.async.commit_group;" ::: "memory")
#define CP_WAIT2()  asm volatile("cp.async.wait_group 2;" ::: "memory")

// mma m16n8k16 fp16 inputs, fp32 accumulate (in place)
__device__ __forceinline__ void mma_f16(float* c,
                                        uint32_t a0, uint32_t a1,
                                        uint32_t a2, uint32_t a3,
                                        uint32_t b0, uint32_t b1) {
    asm volatile(
        "mma.sync.aligned.m16n8k16.row.col.f32.f16.f16.f32 "
        "{%0,%1,%2,%3}, {%4,%5,%6,%7}, {%8,%9}, {%0,%1,%2,%3};"
        : "+f"(c[0]), "+f"(c[1]), "+f"(c[2]), "+f"(c[3])
        : "r"(a0), "r"(a1), "r"(a2), "r"(a3), "r"(b0), "r"(b1));
}

// ldmatrix x4 (b16): four 8x8 tiles, one per 8-lane group
__device__ __forceinline__ void ldsm_x4(uint32_t& r0, uint32_t& r1,
                                        uint32_t& r2, uint32_t& r3,
                                        uint32_t addr) {
    asm volatile("ldmatrix.sync.aligned.m8n8.x4.shared.b16 {%0,%1,%2,%3}, [%4];"
                 : "=r"(r0), "=r"(r1), "=r"(r2), "=r"(r3) : "r"(addr));
}

// ---------------------------------------------------------------------------
// fp16 GEMM (NT): C[M,N] = out_scale*(A[M,K] * B[N,K]^T) + bias_scale*(b1+b2)
// OutT = float (direct full-sector float2 epilogue) or __half (smem-staged
// full-sector epilogue). Block 128x128, BK=32, 8 warps (2x4), warp 64x32.
// cp.async 4-stage pipeline (wait_group 2); ldmatrix fragment loads.
// smem rows: 32 fp16 = 64B data + 16B pad = 80B (conflict-free LDSM phases).
// Requires M%128==0, N%128==0, K%32==0, K/32 >= 3.
// ---------------------------------------------------------------------------
#define ROWB   80
#define TILE_B (128 * ROWB)        // 10240
#define STAGE_B (2 * TILE_B)       // 20480 (A, B)
#define NSTAGE 4
#define SMEM_GEMM (512 + NSTAGE * STAGE_B)   // 82432
#define CPITCH 272                  // fp16 C-stage pitch: 256B data + 16B pad

template <typename OutT>
__global__ __launch_bounds__(256, 2)
void gemm_f16(const __half* __restrict__ A,
              const __half* __restrict__ Bw,
              const float* __restrict__ bias1,
              const float* __restrict__ bias2,
              OutT* __restrict__ C,
              int M, int N, int K, float out_scale, float bias_scale)
{
    extern __shared__ char smem[];
    float* biasS = (float*)smem;
    char* tiles = smem + 512;
    const uint32_t tilesU = smem_u32(tiles);

    const int tid  = threadIdx.x;
    const int wid  = tid >> 5;
    const int lane = tid & 31;
    const int bm = blockIdx.y * 128;
    const int bn = blockIdx.x * 128;

    const int wm = (wid >> 2) * 64;
    const int wn = (wid & 3) * 32;
    const int g0 = lane >> 2;

    if (tid < 128) {
        float bv = bias1[bn + tid];
        if (bias2) bv += bias2[bn + tid];
        biasS[tid] = bv * bias_scale;
    }

    // cp.async mapping: thread -> rows (tid>>2) and (tid>>2)+64, col (tid&3)*16B
    const int crow = tid >> 2;
    const size_t rstride = (size_t)K * 2;   // bytes per gmem row
    const int ccol = (tid & 3) * 16;

    const char* Ag = (const char*)A  + (size_t)(bm + crow) * rstride + ccol;
    const char* Bg = (const char*)Bw + (size_t)(bn + crow) * rstride + ccol;
    const size_t r64 = 64 * rstride;

    const uint32_t sbase = tilesU + crow * ROWB + (tid & 3) * 16;

    // ldmatrix per-lane base addresses (within stage 0)
    const uint32_t aAddr = tilesU + (wm + (lane & 15)) * ROWB + (lane >> 4) * 16;
    const uint32_t bAddr = tilesU + TILE_B
                         + (wn + (lane >> 4) * 8 + (lane & 7)) * ROWB
                         + ((lane >> 3) & 1) * 16;

    float acc[4][4][4];
    #pragma unroll
    for (int mt = 0; mt < 4; mt++)
        #pragma unroll
        for (int nt = 0; nt < 4; nt++)
            #pragma unroll
            for (int j = 0; j < 4; j++)
                acc[mt][nt][j] = 0.0f;

    const int NK = K >> 5;

    auto load_stage = [&](int s, int kt) {
        uint32_t d = sbase + s * STAGE_B;
        size_t go = (size_t)kt * 64;     // 32 fp16 = 64 bytes
        cp_async16(d,                 Ag + go);
        cp_async16(d + 64 * ROWB,     Ag + go + r64);
        cp_async16(d + TILE_B,            Bg + go);
        cp_async16(d + TILE_B + 64 * ROWB, Bg + go + r64);
    };

    load_stage(0, 0); CP_COMMIT();
    load_stage(1, 1); CP_COMMIT();
    load_stage(2, 2); CP_COMMIT();

    for (int kt = 0; kt < NK; kt++) {
        CP_WAIT2();          // stage kt landed (kt+1, kt+2 may be in flight)
        __syncthreads();     // prev iter's MMAs done -> buffer (kt+3)%4 free

        if (kt + 3 < NK) load_stage((kt + 3) & 3, kt + 3);
        CP_COMMIT();         // unconditional: keeps group counting aligned

        const uint32_t stU = (kt & 3) * STAGE_B;

        #pragma unroll
        for (int ko = 0; ko < 2; ko++) {
            const uint32_t kb = stU + ko * 32;

            uint32_t Af[4][4];
            #pragma unroll
            for (int mt = 0; mt < 4; mt++)
                ldsm_x4(Af[mt][0], Af[mt][1], Af[mt][2], Af[mt][3],
                        aAddr + kb + mt * (16 * ROWB));

            uint32_t Bf[2][4];
            #pragma unroll
            for (int np = 0; np < 2; np++)
                ldsm_x4(Bf[np][0], Bf[np][1], Bf[np][2], Bf[np][3],
                        bAddr + kb + np * (16 * ROWB));

            #pragma unroll
            for (int mt = 0; mt < 4; mt++)
                #pragma unroll
                for (int nt = 0; nt < 4; nt++) {
                    const int np = nt >> 1, pr = (nt & 1) * 2;
                    mma_f16(acc[mt][nt],
                            Af[mt][0], Af[mt][1], Af[mt][2], Af[mt][3],
                            Bf[np][pr], Bf[np][pr + 1]);
                }
        }
    }

    const int c0 = (lane & 3) * 2;

    if constexpr (sizeof(OutT) == 4) {
        // fp32: direct float2 stores (4 lanes x 8B = full 32B sectors)
        #pragma unroll
        for (int mt = 0; mt < 4; mt++) {
            #pragma unroll
            for (int nt = 0; nt < 4; nt++) {
                int colL = wn + nt * 8 + c0;
                int col  = bn + colL;
                float b0v = biasS[colL];
                float b1v = biasS[colL + 1];
                int row0 = bm + wm + mt * 16 + g0;
                float2 v0 = make_float2(fmaf(acc[mt][nt][0], out_scale, b0v),
                                        fmaf(acc[mt][nt][1], out_scale, b1v));
                float2 v1 = make_float2(fmaf(acc[mt][nt][2], out_scale, b0v),
                                        fmaf(acc[mt][nt][3], out_scale, b1v));
                *(float2*)((float*)C + (size_t)row0 * N + col)       = v0;
                *(float2*)((float*)C + (size_t)(row0 + 8) * N + col) = v1;
            }
        }
    } else {
        // fp16: stage through smem (pitch 272B, conflict-free), then
        // 16B copy-out -> full-sector gmem stores (no read-modify-write).
        __syncthreads();     // all MMAs done; safe to reuse tile smem
        char* cbuf = tiles;  // 128 * 272 = 34816 <= NSTAGE*STAGE_B
        #pragma unroll
        for (int mt = 0; mt < 4; mt++) {
            #pragma unroll
            for (int nt = 0; nt < 4; nt++) {
                int colL = wn + nt * 8 + c0;
                float b0v = biasS[colL];
                float b1v = biasS[colL + 1];
                int r0 = wm + mt * 16 + g0;
                __half2 v0 = __floats2half2_rn(
                    fmaf(acc[mt][nt][0], out_scale, b0v),
                    fmaf(acc[mt][nt][1], out_scale, b1v));
                __half2 v1 = __floats2half2_rn(
                    fmaf(acc[mt][nt][2], out_scale, b0v),
                    fmaf(acc[mt][nt][3], out_scale, b1v));
                *(__half2*)(cbuf + r0 * CPITCH + colL * 2)       = v0;
                *(__half2*)(cbuf + (r0 + 8) * CPITCH + colL * 2) = v1;
            }
        }
        __syncthreads();
        // 128 rows x 256B = 2048 16B-chunks; 8 per thread.
        #pragma unroll
        for (int k = 0; k < 8; k++) {
            int c = tid + k * 256;
            int row = c >> 4;
            int off = (c & 15) * 16;
            uint4 v = *(uint4*)(cbuf + row * CPITCH + off);
            *(uint4*)((char*)C + ((size_t)(bm + row) * N + bn) * 2 + off) = v;
        }
    }
}

// ---------------------------------------------------------------------------
// IndRNN scan (scaled domain, fp16 in/out):
//   O[b,t,h] = relu(P[b,t,h] + u[h]*O[b,t-1,h])   (values pre-scaled)
// U=32 with next-block prefetch (32 outstanding loads per thread).
// ---------------------------------------------------------------------------
__global__ void scan_relu_f16(const __half* __restrict__ P,
                              const float* __restrict__ u,
                              __half* __restrict__ O)
{
    int idx = blockIdx.x * blockDim.x + threadIdx.x;
    if (idx >= BB * HH) return;
    int b = idx / HH;
    int h = idx - b * HH;
    float uu = u[h];
    float hv = 0.0f;
    const __half* p = P + (size_t)b * TT * HH + h;
    __half* o = O + (size_t)b * TT * HH + h;

    constexpr int U = 32;
    float x[U];
    #pragma unroll
    for (int i = 0; i < U; i++) x[i] = __half2float(p[(size_t)i * HH]);

    #pragma unroll 1
    for (int t = 0; t < TT; t += U) {
        float y[U];
        bool more = (t + U) < TT;
        const __half* pn = p + (size_t)U * HH;
        if (more) {
            #pragma unroll
            for (int i = 0; i < U; i++) y[i] = __half2float(pn[(size_t)i * HH]);
        }
        #pragma unroll
        for (int i = 0; i < U; i++) {
            hv = fmaxf(fmaf(uu, hv, x[i]), 0.0f);
            o[(size_t)i * HH] = __float2half_rn(hv);
        }
        #pragma unroll
        for (int i = 0; i < U; i++) x[i] = y[i];
        p = pn;
        o += (size_t)U * HH;
    }
}

// ---------------------------------------------------------------------------
// Converters
// ---------------------------------------------------------------------------
__global__ void f32_to_f16(const float* __restrict__ in,
                           __half* __restrict__ out, int n)
{
    int i = (blockIdx.x * blockDim.x + threadIdx.x) * 4;
    if (i < n) {
        float4 v = *(const float4*)(in + i);
        __half2 h0 = __floats2half2_rn(v.x, v.y);
        __half2 h1 = __floats2half2_rn(v.z, v.w);
        *(uint2*)(out + i) = make_uint2(*(uint32_t*)&h0, *(uint32_t*)&h1);
    }
}

__global__ void convert_weights(const float* __restrict__ W0,
                                const float* __restrict__ W1,
                                const float* __restrict__ FW,
                                __half* __restrict__ w0,
                                __half* __restrict__ w1,
                                __half* __restrict__ fw)
{
    constexpr int n0 = HH * DIN;           // 65536
    constexpr int n1 = HH * HH;            // 262144
    constexpr int n2 = DOUT * HH;          // 65536
    int i = (blockIdx.x * blockDim.x + threadIdx.x) * 4;
    const float* src;
    __half* dst;
    int j;
    if (i < n0)           { src = W0; dst = w0; j = i; }
    else if (i < n0 + n1) { src = W1; dst = w1; j = i - n0; }
    else if (i < n0 + n1 + n2) { src = FW; dst = fw; j = i - n0 - n1; }
    else return;
    float4 v = *(const float4*)(src + j);
    __half2 h0 = __floats2half2_rn(v.x, v.y);
    __half2 h1 = __floats2half2_rn(v.z, v.w);
    *(uint2*)(dst + j) = make_uint2(*(uint32_t*)&h0, *(uint32_t*)&h1);
}

extern "C" void kernel_launch(void* const* d_in, const int* in_sizes, int n_in,
                              void* d_out, int out_size)
{
    const float* x    = (const float*)d_in[0];
    const float* W0   = (const float*)d_in[1];
    const float* bl0  = (const float*)d_in[2];
    const float* u0   = (const float*)d_in[3];
    const float* bb0  = (const float*)d_in[4];
    const float* W1   = (const float*)d_in[5];
    const float* bl1  = (const float*)d_in[6];
    const float* u1   = (const float*)d_in[7];
    const float* bb1  = (const float*)d_in[8];
    const float* fcW  = (const float*)d_in[9];
    const float* fcb  = (const float*)d_in[10];
    float* out = (float*)d_out;

    __half *proj, *act, *x16, *w0, *w1, *fw;
    cudaGetSymbolAddress((void**)&proj, g_proj);
    cudaGetSymbolAddress((void**)&act,  g_act);
    cudaGetSymbolAddress((void**)&x16,  g_x16);
    cudaGetSymbolAddress((void**)&w0,   g_w0);
    cudaGetSymbolAddress((void**)&w1,   g_w1);
    cudaGetSymbolAddress((void**)&fw,   g_fw);

    cudaFuncSetAttribute(gemm_f16<__half>,
                         cudaFuncAttributeMaxDynamicSharedMemorySize,
                         SMEM_GEMM);
    cudaFuncSetAttribute(gemm_f16<float>,
                         cudaFuncAttributeMaxDynamicSharedMemorySize,
                         SMEM_GEMM);

    // All weights -> fp16 in one launch
    {
        int total = HH * DIN + HH * HH + DOUT * HH;   // 393216
        convert_weights<<<(total / 4 + 255) / 256, 256>>>(W0, W1, fcW,
                                                          w0, w1, fw);
    }
    // x -> fp16
    {
        int n = MM * DIN;
        f32_to_f16<<<(n / 4 + 255) / 256, 256>>>(x, x16, n);
    }

    // Layer 0 in the x2^-4 domain:
    // GEMM0: proj = (x@W0^T + bl0 + bb0) * 2^-4   (fp16, staged epilogue)
    {
        dim3 grid(HH / 128, MM / 128);
        gemm_f16<__half><<<grid, 256, SMEM_GEMM>>>(x16, w0, bl0, bb0, proj,
                                                   MM, HH, DIN,
                                                   0.0625f, 0.0625f);
    }
    // scan0: act = h1 * 2^-4 (relu is positively homogeneous)
    scan_relu_f16<<<(BB * HH) / 128, 128>>>(proj, u0, act);

    // Layer 1 in the x2^-8 domain:
    // GEMM1: proj = (h1*2^-4)@W1^T * 2^-4 + (bl1+bb1)*2^-8 = proj1 * 2^-8
    {
        dim3 grid(HH / 128, MM / 128);
        gemm_f16<__half><<<grid, 256, SMEM_GEMM>>>(act, w1, bl1, bb1, proj,
                                                   MM, HH, HH,
                                                   0.0625f, 0.00390625f);
    }
    // scan1: act = h2 * 2^-8
    scan_relu_f16<<<(BB * HH) / 128, 128>>>(proj, u1, act);

    // GEMM2: out = (h2*2^-8)@fcW^T * 256 + fcb   (fp32 out, direct epilogue)
    {
        dim3 grid(DOUT / 128, MM / 128);
        gemm_f16<float><<<grid, 256, SMEM_GEMM>>>(act, fw, fcb, nullptr, out,
                                                  MM, DOUT, HH,
                                                  256.0f, 1.0f);
    }
}

// round 15
// speedup vs baseline: 1.1476x; 1.0375x over previous
#include <cuda_runtime.h>
#include <cuda_fp16.h>
#include <cstdint>
#include <cstddef>

// Problem constants (fixed by the reference)
#define BB 64
#define TT 2048
#define DIN 128
#define HH 512
#define DOUT 128
#define MM (BB * TT)   // 131072

// Scratch buffers (allocation-guard-safe __device__ globals)
__device__ __align__(256) __half g_proj[(size_t)MM * HH];   // fp16 proj (scaled)
__device__ __align__(256) __half g_act[(size_t)MM * HH];    // fp16 activations (scaled)
__device__ __align__(256) __half g_x16[(size_t)MM * DIN];   // fp16 x
__device__ __align__(256) __half g_w0[HH * DIN];
__device__ __align__(256) __half g_w1[HH * HH];
__device__ __align__(256) __half g_fw[DOUT * HH];

// ---------------------------------------------------------------------------
// PTX helpers
// ---------------------------------------------------------------------------
__device__ __forceinline__ uint32_t smem_u32(const void* p) {
    uint32_t a;
    asm("{ .reg .u64 t; cvta.to.shared.u64 t, %1; cvt.u32.u64 %0, t; }"
        : "=r"(a) : "l"(p));
    return a;
}

__device__ __forceinline__ void cp_async16(uint32_t dst, const void* src) {
    asm volatile("cp.async.cg.shared.global [%0], [%1], 16;"
                 :: "r"(dst), "l"(src));
}
#define CP_COMMIT() asm volatile("cp.async.commit_group;" ::: "memory")
#define CP_WAIT2()  asm volatile("cp.async.wait_group 2;" ::: "memory")

// mma m16n8k16 fp16 inputs, fp32 accumulate (in place)
__device__ __forceinline__ void mma_f16(float* c,
                                        uint32_t a0, uint32_t a1,
                                        uint32_t a2, uint32_t a3,
                                        uint32_t b0, uint32_t b1) {
    asm volatile(
        "mma.sync.aligned.m16n8k16.row.col.f32.f16.f16.f32 "
        "{%0,%1,%2,%3}, {%4,%5,%6,%7}, {%8,%9}, {%0,%1,%2,%3};"
        : "+f"(c[0]), "+f"(c[1]), "+f"(c[2]), "+f"(c[3])
        : "r"(a0), "r"(a1), "r"(a2), "r"(a3), "r"(b0), "r"(b1));
}

// ldmatrix x4 (b16): four 8x8 tiles, one per 8-lane group
__device__ __forceinline__ void ldsm_x4(uint32_t& r0, uint32_t& r1,
                                        uint32_t& r2, uint32_t& r3,
                                        uint32_t addr) {
    asm volatile("ldmatrix.sync.aligned.m8n8.x4.shared.b16 {%0,%1,%2,%3}, [%4];"
                 : "=r"(r0), "=r"(r1), "=r"(r2), "=r"(r3) : "r"(addr));
}

// ---------------------------------------------------------------------------
// fp16 GEMM (NT): C[M,N] = out_scale*(A[M,K] * B[N,K]^T) + bias_scale*(b1+b2)
// OutT = float (direct full-sector float2 epilogue) or __half (smem-staged
// full-sector epilogue). Block 128x128, BK=32, 8 warps (2x4), warp 64x32.
// cp.async 4-stage pipeline (wait_group 2); ldmatrix fragment loads.
// smem rows: 32 fp16 = 64B data + 16B pad = 80B (conflict-free LDSM phases).
// Requires M%128==0, N%128==0, K%32==0, K/32 >= 3.
// ---------------------------------------------------------------------------
#define ROWB   80
#define TILE_B (128 * ROWB)        // 10240
#define STAGE_B (2 * TILE_B)       // 20480 (A, B)
#define NSTAGE 4
#define SMEM_GEMM (512 + NSTAGE * STAGE_B)   // 82432
#define CPITCH 272                  // fp16 C-stage pitch: 256B data + 16B pad

template <typename OutT>
__global__ __launch_bounds__(256, 2)
void gemm_f16(const __half* __restrict__ A,
              const __half* __restrict__ Bw,
              const float* __restrict__ bias1,
              const float* __restrict__ bias2,
              OutT* __restrict__ C,
              int M, int N, int K, float out_scale, float bias_scale)
{
    extern __shared__ char smem[];
    float* biasS = (float*)smem;
    char* tiles = smem + 512;
    const uint32_t tilesU = smem_u32(tiles);

    const int tid  = threadIdx.x;
    const int wid  = tid >> 5;
    const int lane = tid & 31;
    const int bm = blockIdx.y * 128;
    const int bn = blockIdx.x * 128;

    const int wm = (wid >> 2) * 64;
    const int wn = (wid & 3) * 32;
    const int g0 = lane >> 2;

    if (tid < 128) {
        float bv = bias1[bn + tid];
        if (bias2) bv += bias2[bn + tid];
        biasS[tid] = bv * bias_scale;
    }

    // cp.async mapping: thread -> rows (tid>>2) and (tid>>2)+64, col (tid&3)*16B
    const int crow = tid >> 2;
    const size_t rstride = (size_t)K * 2;   // bytes per gmem row
    const int ccol = (tid & 3) * 16;

    const char* Ag = (const char*)A  + (size_t)(bm + crow) * rstride + ccol;
    const char* Bg = (const char*)Bw + (size_t)(bn + crow) * rstride + ccol;
    const size_t r64 = 64 * rstride;

    const uint32_t sbase = tilesU + crow * ROWB + (tid & 3) * 16;

    // ldmatrix per-lane base addresses (within stage 0)
    const uint32_t aAddr = tilesU + (wm + (lane & 15)) * ROWB + (lane >> 4) * 16;
    const uint32_t bAddr = tilesU + TILE_B
                         + (wn + (lane >> 4) * 8 + (lane & 7)) * ROWB
                         + ((lane >> 3) & 1) * 16;

    float acc[4][4][4];
    #pragma unroll
    for (int mt = 0; mt < 4; mt++)
        #pragma unroll
        for (int nt = 0; nt < 4; nt++)
            #pragma unroll
            for (int j = 0; j < 4; j++)
                acc[mt][nt][j] = 0.0f;

    const int NK = K >> 5;

    auto load_stage = [&](int s, int kt) {
        uint32_t d = sbase + s * STAGE_B;
        size_t go = (size_t)kt * 64;     // 32 fp16 = 64 bytes
        cp_async16(d,                 Ag + go);
        cp_async16(d + 64 * ROWB,     Ag + go + r64);
        cp_async16(d + TILE_B,            Bg + go);
        cp_async16(d + TILE_B + 64 * ROWB, Bg + go + r64);
    };

    load_stage(0, 0); CP_COMMIT();
    load_stage(1, 1); CP_COMMIT();
    load_stage(2, 2); CP_COMMIT();

    for (int kt = 0; kt < NK; kt++) {
        CP_WAIT2();          // stage kt landed (kt+1, kt+2 may be in flight)
        __syncthreads();     // prev iter's MMAs done -> buffer (kt+3)%4 free

        if (kt + 3 < NK) load_stage((kt + 3) & 3, kt + 3);
        CP_COMMIT();         // unconditional: keeps group counting aligned

        const uint32_t stU = (kt & 3) * STAGE_B;

        #pragma unroll
        for (int ko = 0; ko < 2; ko++) {
            const uint32_t kb = stU + ko * 32;

            uint32_t Af[4][4];
            #pragma unroll
            for (int mt = 0; mt < 4; mt++)
                ldsm_x4(Af[mt][0], Af[mt][1], Af[mt][2], Af[mt][3],
                        aAddr + kb + mt * (16 * ROWB));

            uint32_t Bf[2][4];
            #pragma unroll
            for (int np = 0; np < 2; np++)
                ldsm_x4(Bf[np][0], Bf[np][1], Bf[np][2], Bf[np][3],
                        bAddr + kb + np * (16 * ROWB));

            #pragma unroll
            for (int mt = 0; mt < 4; mt++)
                #pragma unroll
                for (int nt = 0; nt < 4; nt++) {
                    const int np = nt >> 1, pr = (nt & 1) * 2;
                    mma_f16(acc[mt][nt],
                            Af[mt][0], Af[mt][1], Af[mt][2], Af[mt][3],
                            Bf[np][pr], Bf[np][pr + 1]);
                }
        }
    }

    const int c0 = (lane & 3) * 2;

    if constexpr (sizeof(OutT) == 4) {
        // fp32: direct float2 stores (4 lanes x 8B = full 32B sectors)
        #pragma unroll
        for (int mt = 0; mt < 4; mt++) {
            #pragma unroll
            for (int nt = 0; nt < 4; nt++) {
                int colL = wn + nt * 8 + c0;
                int col  = bn + colL;
                float b0v = biasS[colL];
                float b1v = biasS[colL + 1];
                int row0 = bm + wm + mt * 16 + g0;
                float2 v0 = make_float2(fmaf(acc[mt][nt][0], out_scale, b0v),
                                        fmaf(acc[mt][nt][1], out_scale, b1v));
                float2 v1 = make_float2(fmaf(acc[mt][nt][2], out_scale, b0v),
                                        fmaf(acc[mt][nt][3], out_scale, b1v));
                *(float2*)((float*)C + (size_t)row0 * N + col)       = v0;
                *(float2*)((float*)C + (size_t)(row0 + 8) * N + col) = v1;
            }
        }
    } else {
        // fp16: stage through smem (pitch 272B, conflict-free), then
        // 16B copy-out -> full-sector gmem stores (no read-modify-write).
        __syncthreads();     // all MMAs done; safe to reuse tile smem
        char* cbuf = tiles;  // 128 * 272 = 34816 <= NSTAGE*STAGE_B
        #pragma unroll
        for (int mt = 0; mt < 4; mt++) {
            #pragma unroll
            for (int nt = 0; nt < 4; nt++) {
                int colL = wn + nt * 8 + c0;
                float b0v = biasS[colL];
                float b1v = biasS[colL + 1];
                int r0 = wm + mt * 16 + g0;
                __half2 v0 = __floats2half2_rn(
                    fmaf(acc[mt][nt][0], out_scale, b0v),
                    fmaf(acc[mt][nt][1], out_scale, b1v));
                __half2 v1 = __floats2half2_rn(
                    fmaf(acc[mt][nt][2], out_scale, b0v),
                    fmaf(acc[mt][nt][3], out_scale, b1v));
                *(__half2*)(cbuf + r0 * CPITCH + colL * 2)       = v0;
                *(__half2*)(cbuf + (r0 + 8) * CPITCH + colL * 2) = v1;
            }
        }
        __syncthreads();
        // 128 rows x 256B = 2048 16B-chunks; 8 per thread.
        #pragma unroll
        for (int k = 0; k < 8; k++) {
            int c = tid + k * 256;
            int row = c >> 4;
            int off = (c & 15) * 16;
            uint4 v = *(uint4*)(cbuf + row * CPITCH + off);
            *(uint4*)((char*)C + ((size_t)(bm + row) * N + bn) * 2 + off) = v;
        }
    }
}

// ---------------------------------------------------------------------------
// IndRNN scan (scaled domain), __half2 vectorized: each thread owns TWO
// adjacent h-channels. One LDG.32/STG.32 per t-step (full 128B warp
// wavefronts), fp32 math (bit-identical to the scalar version).
//   O2[b,t,h2] = relu2(P2[b,t,h2] + u2[h2]*O2[b,t-1,h2])
// ---------------------------------------------------------------------------
#define H2 (HH / 2)   // 256 half2 channels per batch

__global__ void scan_relu_f16v2(const __half2* __restrict__ P,
                                const float* __restrict__ u,
                                __half2* __restrict__ O)
{
    int idx = blockIdx.x * blockDim.x + threadIdx.x;   // 0 .. BB*H2-1
    if (idx >= BB * H2) return;
    int b  = idx / H2;
    int h2 = idx - b * H2;
    float u0 = u[h2 * 2];
    float u1 = u[h2 * 2 + 1];
    float hv0 = 0.0f, hv1 = 0.0f;
    const __half2* p = P + (size_t)b * TT * H2 + h2;
    __half2* o = O + (size_t)b * TT * H2 + h2;

    constexpr int U = 32;
    __half2 x[U];
    #pragma unroll
    for (int i = 0; i < U; i++) x[i] = p[(size_t)i * H2];

    #pragma unroll 1
    for (int t = 0; t < TT; t += U) {
        __half2 y[U];
        bool more = (t + U) < TT;
        const __half2* pn = p + (size_t)U * H2;
        if (more) {
            #pragma unroll
            for (int i = 0; i < U; i++) y[i] = pn[(size_t)i * H2];
        }
        #pragma unroll
        for (int i = 0; i < U; i++) {
            float2 f = __half22float2(x[i]);
            hv0 = fmaxf(fmaf(u0, hv0, f.x), 0.0f);
            hv1 = fmaxf(fmaf(u1, hv1, f.y), 0.0f);
            o[(size_t)i * H2] = __floats2half2_rn(hv0, hv1);
        }
        #pragma unroll
        for (int i = 0; i < U; i++) x[i] = y[i];
        p = pn;
        o += (size_t)U * H2;
    }
}

// ---------------------------------------------------------------------------
// Converters
// ---------------------------------------------------------------------------
__global__ void f32_to_f16(const float* __restrict__ in,
                           __half* __restrict__ out, int n)
{
    int i = (blockIdx.x * blockDim.x + threadIdx.x) * 4;
    if (i < n) {
        float4 v = *(const float4*)(in + i);
        __half2 h0 = __floats2half2_rn(v.x, v.y);
        __half2 h1 = __floats2half2_rn(v.z, v.w);
        *(uint2*)(out + i) = make_uint2(*(uint32_t*)&h0, *(uint32_t*)&h1);
    }
}

__global__ void convert_weights(const float* __restrict__ W0,
                                const float* __restrict__ W1,
                                const float* __restrict__ FW,
                                __half* __restrict__ w0,
                                __half* __restrict__ w1,
                                __half* __restrict__ fw)
{
    constexpr int n0 = HH * DIN;           // 65536
    constexpr int n1 = HH * HH;            // 262144
    constexpr int n2 = DOUT * HH;          // 65536
    int i = (blockIdx.x * blockDim.x + threadIdx.x) * 4;
    const float* src;
    __half* dst;
    int j;
    if (i < n0)           { src = W0; dst = w0; j = i; }
    else if (i < n0 + n1) { src = W1; dst = w1; j = i - n0; }
    else if (i < n0 + n1 + n2) { src = FW; dst = fw; j = i - n0 - n1; }
    else return;
    float4 v = *(const float4*)(src + j);
    __half2 h0 = __floats2half2_rn(v.x, v.y);
    __half2 h1 = __floats2half2_rn(v.z, v.w);
    *(uint2*)(dst + j) = make_uint2(*(uint32_t*)&h0, *(uint32_t*)&h1);
}

extern "C" void kernel_launch(void* const* d_in, const int* in_sizes, int n_in,
                              void* d_out, int out_size)
{
    const float* x    = (const float*)d_in[0];
    const float* W0   = (const float*)d_in[1];
    const float* bl0  = (const float*)d_in[2];
    const float* u0   = (const float*)d_in[3];
    const float* bb0  = (const float*)d_in[4];
    const float* W1   = (const float*)d_in[5];
    const float* bl1  = (const float*)d_in[6];
    const float* u1   = (const float*)d_in[7];
    const float* bb1  = (const float*)d_in[8];
    const float* fcW  = (const float*)d_in[9];
    const float* fcb  = (const float*)d_in[10];
    float* out = (float*)d_out;

    __half *proj, *act, *x16, *w0, *w1, *fw;
    cudaGetSymbolAddress((void**)&proj, g_proj);
    cudaGetSymbolAddress((void**)&act,  g_act);
    cudaGetSymbolAddress((void**)&x16,  g_x16);
    cudaGetSymbolAddress((void**)&w0,   g_w0);
    cudaGetSymbolAddress((void**)&w1,   g_w1);
    cudaGetSymbolAddress((void**)&fw,   g_fw);

    cudaFuncSetAttribute(gemm_f16<__half>,
                         cudaFuncAttributeMaxDynamicSharedMemorySize,
                         SMEM_GEMM);
    cudaFuncSetAttribute(gemm_f16<float>,
                         cudaFuncAttributeMaxDynamicSharedMemorySize,
                         SMEM_GEMM);

    // All weights -> fp16 in one launch
    {
        int total = HH * DIN + HH * HH + DOUT * HH;   // 393216
        convert_weights<<<(total / 4 + 255) / 256, 256>>>(W0, W1, fcW,
                                                          w0, w1, fw);
    }
    // x -> fp16
    {
        int n = MM * DIN;
        f32_to_f16<<<(n / 4 + 255) / 256, 256>>>(x, x16, n);
    }

    // Layer 0 in the x2^-4 domain:
    // GEMM0: proj = (x@W0^T + bl0 + bb0) * 2^-4   (fp16, staged epilogue)
    {
        dim3 grid(HH / 128, MM / 128);
        gemm_f16<__half><<<grid, 256, SMEM_GEMM>>>(x16, w0, bl0, bb0, proj,
                                                   MM, HH, DIN,
                                                   0.0625f, 0.0625f);
    }
    // scan0: act = h1 * 2^-4 (relu is positively homogeneous)
    scan_relu_f16v2<<<(BB * H2) / 64, 64>>>((const __half2*)proj, u0,
                                            (__half2*)act);

    // Layer 1 in the x2^-8 domain:
    // GEMM1: proj = (h1*2^-4)@W1^T * 2^-4 + (bl1+bb1)*2^-8 = proj1 * 2^-8
    {
        dim3 grid(HH / 128, MM / 128);
        gemm_f16<__half><<<grid, 256, SMEM_GEMM>>>(act, w1, bl1, bb1, proj,
                                                   MM, HH, HH,
                                                   0.0625f, 0.00390625f);
    }
    // scan1: act = h2 * 2^-8
    scan_relu_f16v2<<<(BB * H2) / 64, 64>>>((const __half2*)proj, u1,
                                            (__half2*)act);

    // GEMM2: out = (h2*2^-8)@fcW^T * 256 + fcb   (fp32 out, direct epilogue)
    {
        dim3 grid(DOUT / 128, MM / 128);
        gemm_f16<float><<<grid, 256, SMEM_GEMM>>>(act, fw, fcb, nullptr, out,
                                                  MM, DOUT, HH,
                                                  256.0f, 1.0f);
    }
}

// round 16
// speedup vs baseline: 1.1550x; 1.0065x over previous
#include <cuda_runtime.h>
#include <cuda_fp16.h>
#include <cstdint>
#include <cstddef>

// Problem constants (fixed by the reference)
#define BB 64
#define TT 2048
#define DIN 128
#define HH 512
#define DOUT 128
#define MM (BB * TT)   // 131072

// Scratch buffers (allocation-guard-safe __device__ globals)
__device__ __align__(256) __half g_proj[(size_t)MM * HH];   // fp16 proj (scaled)
__device__ __align__(256) __half g_act[(size_t)MM * HH];    // fp16 activations (scaled)
__device__ __align__(256) __half g_x16[(size_t)MM * DIN];   // fp16 x
__device__ __align__(256) __half g_w0[HH * DIN];
__device__ __align__(256) __half g_w1[HH * HH];
__device__ __align__(256) __half g_fw[DOUT * HH];

// ---------------------------------------------------------------------------
// PTX helpers
// ---------------------------------------------------------------------------
__device__ __forceinline__ uint32_t smem_u32(const void* p) {
    uint32_t a;
    asm("{ .reg .u64 t; cvta.to.shared.u64 t, %1; cvt.u32.u64 %0, t; }"
        : "=r"(a) : "l"(p));
    return a;
}

__device__ __forceinline__ void cp_async16(uint32_t dst, const void* src) {
    asm volatile("cp.async.cg.shared.global [%0], [%1], 16;"
                 :: "r"(dst), "l"(src));
}
#define CP_COMMIT() asm volatile("cp.async.commit_group;" ::: "memory")
#define CP_WAIT2()  asm volatile("cp.async.wait_group 2;" ::: "memory")

// mma m16n8k16 fp16 inputs, fp32 accumulate (in place)
__device__ __forceinline__ void mma_f16(float* c,
                                        uint32_t a0, uint32_t a1,
                                        uint32_t a2, uint32_t a3,
                                        uint32_t b0, uint32_t b1) {
    asm volatile(
        "mma.sync.aligned.m16n8k16.row.col.f32.f16.f16.f32 "
        "{%0,%1,%2,%3}, {%4,%5,%6,%7}, {%8,%9}, {%0,%1,%2,%3};"
        : "+f"(c[0]), "+f"(c[1]), "+f"(c[2]), "+f"(c[3])
        : "r"(a0), "r"(a1), "r"(a2), "r"(a3), "r"(b0), "r"(b1));
}

// ldmatrix x4 (b16): four 8x8 tiles, one per 8-lane group
__device__ __forceinline__ void ldsm_x4(uint32_t& r0, uint32_t& r1,
                                        uint32_t& r2, uint32_t& r3,
                                        uint32_t addr) {
    asm volatile("ldmatrix.sync.aligned.m8n8.x4.shared.b16 {%0,%1,%2,%3}, [%4];"
                 : "=r"(r0), "=r"(r1), "=r"(r2), "=r"(r3) : "r"(addr));
}

// ---------------------------------------------------------------------------
// fp16 GEMM (NT): C[M,N] = out_scale*(A[M,K] * B[N,K]^T) + bias_scale*(b1+b2)
// OutT = float (direct full-sector float2 epilogue) or __half (smem-staged
// full-sector epilogue). Block 128x128, BK=32, 8 warps (2x4), warp 64x32.
// cp.async 4-stage pipeline (wait_group 2); ldmatrix fragment loads.
// smem rows: 32 fp16 = 64B data + 16B pad = 80B (conflict-free LDSM phases).
// Requires M%128==0, N%128==0, K%32==0, K/32 >= 3.
// ---------------------------------------------------------------------------
#define ROWB   80
#define TILE_B (128 * ROWB)        // 10240
#define STAGE_B (2 * TILE_B)       // 20480 (A, B)
#define NSTAGE 4
#define SMEM_GEMM (512 + NSTAGE * STAGE_B)   // 82432
#define CPITCH 272                  // fp16 C-stage pitch: 256B data + 16B pad

template <typename OutT>
__global__ __launch_bounds__(256, 2)
void gemm_f16(const __half* __restrict__ A,
              const __half* __restrict__ Bw,
              const float* __restrict__ bias1,
              const float* __restrict__ bias2,
              OutT* __restrict__ C,
              int M, int N, int K, float out_scale, float bias_scale)
{
    extern __shared__ char smem[];
    float* biasS = (float*)smem;
    char* tiles = smem + 512;
    const uint32_t tilesU = smem_u32(tiles);

    const int tid  = threadIdx.x;
    const int wid  = tid >> 5;
    const int lane = tid & 31;
    const int bm = blockIdx.y * 128;
    const int bn = blockIdx.x * 128;

    const int wm = (wid >> 2) * 64;
    const int wn = (wid & 3) * 32;
    const int g0 = lane >> 2;

    if (tid < 128) {
        float bv = bias1[bn + tid];
        if (bias2) bv += bias2[bn + tid];
        biasS[tid] = bv * bias_scale;
    }

    // cp.async mapping: thread -> rows (tid>>2) and (tid>>2)+64, col (tid&3)*16B
    const int crow = tid >> 2;
    const size_t rstride = (size_t)K * 2;   // bytes per gmem row
    const int ccol = (tid & 3) * 16;

    const char* Ag = (const char*)A  + (size_t)(bm + crow) * rstride + ccol;
    const char* Bg = (const char*)Bw + (size_t)(bn + crow) * rstride + ccol;
    const size_t r64 = 64 * rstride;

    const uint32_t sbase = tilesU + crow * ROWB + (tid & 3) * 16;

    // ldmatrix per-lane base addresses (within stage 0)
    const uint32_t aAddr = tilesU + (wm + (lane & 15)) * ROWB + (lane >> 4) * 16;
    const uint32_t bAddr = tilesU + TILE_B
                         + (wn + (lane >> 4) * 8 + (lane & 7)) * ROWB
                         + ((lane >> 3) & 1) * 16;

    float acc[4][4][4];
    #pragma unroll
    for (int mt = 0; mt < 4; mt++)
        #pragma unroll
        for (int nt = 0; nt < 4; nt++)
            #pragma unroll
            for (int j = 0; j < 4; j++)
                acc[mt][nt][j] = 0.0f;

    const int NK = K >> 5;

    auto load_stage = [&](int s, int kt) {
        uint32_t d = sbase + s * STAGE_B;
        size_t go = (size_t)kt * 64;     // 32 fp16 = 64 bytes
        cp_async16(d,                 Ag + go);
        cp_async16(d + 64 * ROWB,     Ag + go + r64);
        cp_async16(d + TILE_B,            Bg + go);
        cp_async16(d + TILE_B + 64 * ROWB, Bg + go + r64);
    };

    load_stage(0, 0); CP_COMMIT();
    load_stage(1, 1); CP_COMMIT();
    load_stage(2, 2); CP_COMMIT();

    for (int kt = 0; kt < NK; kt++) {
        CP_WAIT2();          // stage kt landed (kt+1, kt+2 may be in flight)
        __syncthreads();     // prev iter's MMAs done -> buffer (kt+3)%4 free

        if (kt + 3 < NK) load_stage((kt + 3) & 3, kt + 3);
        CP_COMMIT();         // unconditional: keeps group counting aligned

        const uint32_t stU = (kt & 3) * STAGE_B;

        #pragma unroll
        for (int ko = 0; ko < 2; ko++) {
            const uint32_t kb = stU + ko * 32;

            uint32_t Af[4][4];
            #pragma unroll
            for (int mt = 0; mt < 4; mt++)
                ldsm_x4(Af[mt][0], Af[mt][1], Af[mt][2], Af[mt][3],
                        aAddr + kb + mt * (16 * ROWB));

            uint32_t Bf[2][4];
            #pragma unroll
            for (int np = 0; np < 2; np++)
                ldsm_x4(Bf[np][0], Bf[np][1], Bf[np][2], Bf[np][3],
                        bAddr + kb + np * (16 * ROWB));

            #pragma unroll
            for (int mt = 0; mt < 4; mt++)
                #pragma unroll
                for (int nt = 0; nt < 4; nt++) {
                    const int np = nt >> 1, pr = (nt & 1) * 2;
                    mma_f16(acc[mt][nt],
                            Af[mt][0], Af[mt][1], Af[mt][2], Af[mt][3],
                            Bf[np][pr], Bf[np][pr + 1]);
                }
        }
    }

    const int c0 = (lane & 3) * 2;

    if constexpr (sizeof(OutT) == 4) {
        // fp32: direct float2 stores (4 lanes x 8B = full 32B sectors)
        #pragma unroll
        for (int mt = 0; mt < 4; mt++) {
            #pragma unroll
            for (int nt = 0; nt < 4; nt++) {
                int colL = wn + nt * 8 + c0;
                int col  = bn + colL;
                float b0v = biasS[colL];
                float b1v = biasS[colL + 1];
                int row0 = bm + wm + mt * 16 + g0;
                float2 v0 = make_float2(fmaf(acc[mt][nt][0], out_scale, b0v),
                                        fmaf(acc[mt][nt][1], out_scale, b1v));
                float2 v1 = make_float2(fmaf(acc[mt][nt][2], out_scale, b0v),
                                        fmaf(acc[mt][nt][3], out_scale, b1v));
                *(float2*)((float*)C + (size_t)row0 * N + col)       = v0;
                *(float2*)((float*)C + (size_t)(row0 + 8) * N + col) = v1;
            }
        }
    } else {
        // fp16: stage through smem (pitch 272B, conflict-free), then
        // 16B copy-out -> full-sector gmem stores (no read-modify-write).
        __syncthreads();     // all MMAs done; safe to reuse tile smem
        char* cbuf = tiles;  // 128 * 272 = 34816 <= NSTAGE*STAGE_B
        #pragma unroll
        for (int mt = 0; mt < 4; mt++) {
            #pragma unroll
            for (int nt = 0; nt < 4; nt++) {
                int colL = wn + nt * 8 + c0;
                float b0v = biasS[colL];
                float b1v = biasS[colL + 1];
                int r0 = wm + mt * 16 + g0;
                __half2 v0 = __floats2half2_rn(
                    fmaf(acc[mt][nt][0], out_scale, b0v),
                    fmaf(acc[mt][nt][1], out_scale, b1v));
                __half2 v1 = __floats2half2_rn(
                    fmaf(acc[mt][nt][2], out_scale, b0v),
                    fmaf(acc[mt][nt][3], out_scale, b1v));
                *(__half2*)(cbuf + r0 * CPITCH + colL * 2)       = v0;
                *(__half2*)(cbuf + (r0 + 8) * CPITCH + colL * 2) = v1;
            }
        }
        __syncthreads();
        // 128 rows x 256B = 2048 16B-chunks; 8 per thread.
        #pragma unroll
        for (int k = 0; k < 8; k++) {
            int c = tid + k * 256;
            int row = c >> 4;
            int off = (c & 15) * 16;
            uint4 v = *(uint4*)(cbuf + row * CPITCH + off);
            *(uint4*)((char*)C + ((size_t)(bm + row) * N + bn) * 2 + off) = v;
        }
    }
}

// ---------------------------------------------------------------------------
// IndRNN scan (scaled domain), __half2 vectorized, prefetch distance 2:
// each thread owns TWO adjacent h-channels; register blocks x/y/z rotate so
// every load has ~2 U-blocks of compute latency cover.
//   O2[b,t,h2] = relu2(P2[b,t,h2] + u2[h2]*O2[b,t-1,h2])
// ---------------------------------------------------------------------------
#define H2 (HH / 2)   // 256 half2 channels per batch

__global__ void scan_relu_f16v2(const __half2* __restrict__ P,
                                const float* __restrict__ u,
                                __half2* __restrict__ O)
{
    int idx = blockIdx.x * blockDim.x + threadIdx.x;   // 0 .. BB*H2-1
    if (idx >= BB * H2) return;
    int b  = idx / H2;
    int h2 = idx - b * H2;
    float u0 = u[h2 * 2];
    float u1 = u[h2 * 2 + 1];
    float hv0 = 0.0f, hv1 = 0.0f;
    const __half2* p = P + (size_t)b * TT * H2 + h2;
    __half2* o = O + (size_t)b * TT * H2 + h2;

    constexpr int U = 32;
    constexpr int NB = TT / U;   // 64 blocks

    __half2 x[U], y[U];
    #pragma unroll
    for (int i = 0; i < U; i++) x[i] = p[(size_t)i * H2];
    #pragma unroll
    for (int i = 0; i < U; i++) y[i] = p[(size_t)(U + i) * H2];

    #pragma unroll 1
    for (int blk = 0; blk < NB; blk++) {
        __half2 z[U];
        bool more2 = (blk + 2) < NB;
        const __half2* pz = p + (size_t)2 * U * H2;
        if (more2) {
            #pragma unroll
            for (int i = 0; i < U; i++) z[i] = pz[(size_t)i * H2];
        }
        #pragma unroll
        for (int i = 0; i < U; i++) {
            float2 f = __half22float2(x[i]);
            hv0 = fmaxf(fmaf(u0, hv0, f.x), 0.0f);
            hv1 = fmaxf(fmaf(u1, hv1, f.y), 0.0f);
            o[(size_t)i * H2] = __floats2half2_rn(hv0, hv1);
        }
        #pragma unroll
        for (int i = 0; i < U; i++) { x[i] = y[i]; y[i] = z[i]; }
        p += (size_t)U * H2;
        o += (size_t)U * H2;
    }
}

// ---------------------------------------------------------------------------
// Converters
// ---------------------------------------------------------------------------
__global__ void f32_to_f16(const float* __restrict__ in,
                           __half* __restrict__ out, int n)
{
    int i = (blockIdx.x * blockDim.x + threadIdx.x) * 4;
    if (i < n) {
        float4 v = *(const float4*)(in + i);
        __half2 h0 = __floats2half2_rn(v.x, v.y);
        __half2 h1 = __floats2half2_rn(v.z, v.w);
        *(uint2*)(out + i) = make_uint2(*(uint32_t*)&h0, *(uint32_t*)&h1);
    }
}

__global__ void convert_weights(const float* __restrict__ W0,
                                const float* __restrict__ W1,
                                const float* __restrict__ FW,
                                __half* __restrict__ w0,
                                __half* __restrict__ w1,
                                __half* __restrict__ fw)
{
    constexpr int n0 = HH * DIN;           // 65536
    constexpr int n1 = HH * HH;            // 262144
    constexpr int n2 = DOUT * HH;          // 65536
    int i = (blockIdx.x * blockDim.x + threadIdx.x) * 4;
    const float* src;
    __half* dst;
    int j;
    if (i < n0)           { src = W0; dst = w0; j = i; }
    else if (i < n0 + n1) { src = W1; dst = w1; j = i - n0; }
    else if (i < n0 + n1 + n2) { src = FW; dst = fw; j = i - n0 - n1; }
    else return;
    float4 v = *(const float4*)(src + j);
    __half2 h0 = __floats2half2_rn(v.x, v.y);
    __half2 h1 = __floats2half2_rn(v.z, v.w);
    *(uint2*)(dst + j) = make_uint2(*(uint32_t*)&h0, *(uint32_t*)&h1);
}

extern "C" void kernel_launch(void* const* d_in, const int* in_sizes, int n_in,
                              void* d_out, int out_size)
{
    const float* x    = (const float*)d_in[0];
    const float* W0   = (const float*)d_in[1];
    const float* bl0  = (const float*)d_in[2];
    const float* u0   = (const float*)d_in[3];
    const float* bb0  = (const float*)d_in[4];
    const float* W1   = (const float*)d_in[5];
    const float* bl1  = (const float*)d_in[6];
    const float* u1   = (const float*)d_in[7];
    const float* bb1  = (const float*)d_in[8];
    const float* fcW  = (const float*)d_in[9];
    const float* fcb  = (const float*)d_in[10];
    float* out = (float*)d_out;

    __half *proj, *act, *x16, *w0, *w1, *fw;
    cudaGetSymbolAddress((void**)&proj, g_proj);
    cudaGetSymbolAddress((void**)&act,  g_act);
    cudaGetSymbolAddress((void**)&x16,  g_x16);
    cudaGetSymbolAddress((void**)&w0,   g_w0);
    cudaGetSymbolAddress((void**)&w1,   g_w1);
    cudaGetSymbolAddress((void**)&fw,   g_fw);

    cudaFuncSetAttribute(gemm_f16<__half>,
                         cudaFuncAttributeMaxDynamicSharedMemorySize,
                         SMEM_GEMM);
    cudaFuncSetAttribute(gemm_f16<float>,
                         cudaFuncAttributeMaxDynamicSharedMemorySize,
                         SMEM_GEMM);

    // All weights -> fp16 in one launch
    {
        int total = HH * DIN + HH * HH + DOUT * HH;   // 393216
        convert_weights<<<(total / 4 + 255) / 256, 256>>>(W0, W1, fcW,
                                                          w0, w1, fw);
    }
    // x -> fp16
    {
        int n = MM * DIN;
        f32_to_f16<<<(n / 4 + 255) / 256, 256>>>(x, x16, n);
    }

    // Layer 0 in the x2^-4 domain:
    // GEMM0: proj = (x@W0^T + bl0 + bb0) * 2^-4   (fp16, staged epilogue)
    {
        dim3 grid(HH / 128, MM / 128);
        gemm_f16<__half><<<grid, 256, SMEM_GEMM>>>(x16, w0, bl0, bb0, proj,
                                                   MM, HH, DIN,
                                                   0.0625f, 0.0625f);
    }
    // scan0: act = h1 * 2^-4 (relu is positively homogeneous)
    scan_relu_f16v2<<<(BB * H2) / 64, 64>>>((const __half2*)proj, u0,
                                            (__half2*)act);

    // Layer 1 in the x2^-8 domain:
    // GEMM1: proj = (h1*2^-4)@W1^T * 2^-4 + (bl1+bb1)*2^-8 = proj1 * 2^-8
    {
        dim3 grid(HH / 128, MM / 128);
        gemm_f16<__half><<<grid, 256, SMEM_GEMM>>>(act, w1, bl1, bb1, proj,
                                                   MM, HH, HH,
                                                   0.0625f, 0.00390625f);
    }
    // scan1: act = h2 * 2^-8
    scan_relu_f16v2<<<(BB * H2) / 64, 64>>>((const __half2*)proj, u1,
                                            (__half2*)act);

    // GEMM2: out = (h2*2^-8)@fcW^T * 256 + fcb   (fp32 out, direct epilogue)
    {
        dim3 grid(DOUT / 128, MM / 128);
        gemm_f16<float><<<grid, 256, SMEM_GEMM>>>(act, fw, fcb, nullptr, out,
                                                  MM, DOUT, HH,
                                                  256.0f, 1.0f);
    }
}

// round 17
// speedup vs baseline: 1.1590x; 1.0034x over previous
#include <cuda_runtime.h>
#include <cuda_fp16.h>
#include <cstdint>
#include <cstddef>

// Problem constants (fixed by the reference)
#define BB 64
#define TT 2048
#define DIN 128
#define HH 512
#define DOUT 128
#define MM (BB * TT)   // 131072

// Scratch buffers (allocation-guard-safe __device__ globals)
__device__ __align__(256) __half g_proj[(size_t)MM * HH];   // fp16 proj (scaled)
__device__ __align__(256) __half g_act[(size_t)MM * HH];    // fp16 activations (scaled)
__device__ __align__(256) __half g_x16[(size_t)MM * DIN];   // fp16 x
__device__ __align__(256) __half g_w0[HH * DIN];
__device__ __align__(256) __half g_w1[HH * HH];
__device__ __align__(256) __half g_fw[DOUT * HH];

// ---------------------------------------------------------------------------
// PTX helpers
// ---------------------------------------------------------------------------
__device__ __forceinline__ uint32_t smem_u32(const void* p) {
    uint32_t a;
    asm("{ .reg .u64 t; cvta.to.shared.u64 t, %1; cvt.u32.u64 %0, t; }"
        : "=r"(a) : "l"(p));
    return a;
}

__device__ __forceinline__ void cp_async16(uint32_t dst, const void* src) {
    asm volatile("cp.async.cg.shared.global [%0], [%1], 16;"
                 :: "r"(dst), "l"(src));
}
#define CP_COMMIT() asm volatile("cp.async.commit_group;" ::: "memory")
#define CP_WAIT2()  asm volatile("cp.async.wait_group 2;" ::: "memory")

// mma m16n8k16 fp16 inputs, fp32 accumulate (in place)
__device__ __forceinline__ void mma_f16(float* c,
                                        uint32_t a0, uint32_t a1,
                                        uint32_t a2, uint32_t a3,
                                        uint32_t b0, uint32_t b1) {
    asm volatile(
        "mma.sync.aligned.m16n8k16.row.col.f32.f16.f16.f32 "
        "{%0,%1,%2,%3}, {%4,%5,%6,%7}, {%8,%9}, {%0,%1,%2,%3};"
        : "+f"(c[0]), "+f"(c[1]), "+f"(c[2]), "+f"(c[3])
        : "r"(a0), "r"(a1), "r"(a2), "r"(a3), "r"(b0), "r"(b1));
}

// ldmatrix x4 (b16): four 8x8 tiles, one per 8-lane group
__device__ __forceinline__ void ldsm_x4(uint32_t& r0, uint32_t& r1,
                                        uint32_t& r2, uint32_t& r3,
                                        uint32_t addr) {
    asm volatile("ldmatrix.sync.aligned.m8n8.x4.shared.b16 {%0,%1,%2,%3}, [%4];"
                 : "=r"(r0), "=r"(r1), "=r"(r2), "=r"(r3) : "r"(addr));
}

// ---------------------------------------------------------------------------
// fp16 GEMM (NT): C[M,N] = out_scale*(A[M,K] * B[N,K]^T) + bias_scale*(b1+b2)
// OutT = float (direct full-sector float2 epilogue) or __half (smem-staged
// full-sector epilogue). Block 128x128, BK=32, 8 warps (2x4), warp 64x32.
// cp.async 4-stage pipeline (wait_group 2); ldmatrix fragment loads.
// smem rows: 32 fp16 = 64B data + 16B pad = 80B (conflict-free LDSM phases).
// Requires M%128==0, N%128==0, K%32==0, K/32 >= 3.
// ---------------------------------------------------------------------------
#define ROWB   80
#define TILE_B (128 * ROWB)        // 10240
#define STAGE_B (2 * TILE_B)       // 20480 (A, B)
#define NSTAGE 4
#define SMEM_GEMM (512 + NSTAGE * STAGE_B)   // 82432
#define CPITCH 272                  // fp16 C-stage pitch: 256B data + 16B pad

template <typename OutT>
__global__ __launch_bounds__(256, 2)
void gemm_f16(const __half* __restrict__ A,
              const __half* __restrict__ Bw,
              const float* __restrict__ bias1,
              const float* __restrict__ bias2,
              OutT* __restrict__ C,
              int M, int N, int K, float out_scale, float bias_scale)
{
    extern __shared__ char smem[];
    float* biasS = (float*)smem;
    char* tiles = smem + 512;
    const uint32_t tilesU = smem_u32(tiles);

    const int tid  = threadIdx.x;
    const int wid  = tid >> 5;
    const int lane = tid & 31;
    const int bm = blockIdx.y * 128;
    const int bn = blockIdx.x * 128;

    const int wm = (wid >> 2) * 64;
    const int wn = (wid & 3) * 32;
    const int g0 = lane >> 2;

    if (tid < 128) {
        float bv = bias1[bn + tid];
        if (bias2) bv += bias2[bn + tid];
        biasS[tid] = bv * bias_scale;
    }

    // cp.async mapping: thread -> rows (tid>>2) and (tid>>2)+64, col (tid&3)*16B
    const int crow = tid >> 2;
    const size_t rstride = (size_t)K * 2;   // bytes per gmem row
    const int ccol = (tid & 3) * 16;

    const char* Ag = (const char*)A  + (size_t)(bm + crow) * rstride + ccol;
    const char* Bg = (const char*)Bw + (size_t)(bn + crow) * rstride + ccol;
    const size_t r64 = 64 * rstride;

    const uint32_t sbase = tilesU + crow * ROWB + (tid & 3) * 16;

    // ldmatrix per-lane base addresses (within stage 0)
    const uint32_t aAddr = tilesU + (wm + (lane & 15)) * ROWB + (lane >> 4) * 16;
    const uint32_t bAddr = tilesU + TILE_B
                         + (wn + (lane >> 4) * 8 + (lane & 7)) * ROWB
                         + ((lane >> 3) & 1) * 16;

    float acc[4][4][4];
    #pragma unroll
    for (int mt = 0; mt < 4; mt++)
        #pragma unroll
        for (int nt = 0; nt < 4; nt++)
            #pragma unroll
            for (int j = 0; j < 4; j++)
                acc[mt][nt][j] = 0.0f;

    const int NK = K >> 5;

    auto load_stage = [&](int s, int kt) {
        uint32_t d = sbase + s * STAGE_B;
        size_t go = (size_t)kt * 64;     // 32 fp16 = 64 bytes
        cp_async16(d,                 Ag + go);
        cp_async16(d + 64 * ROWB,     Ag + go + r64);
        cp_async16(d + TILE_B,            Bg + go);
        cp_async16(d + TILE_B + 64 * ROWB, Bg + go + r64);
    };

    load_stage(0, 0); CP_COMMIT();
    load_stage(1, 1); CP_COMMIT();
    load_stage(2, 2); CP_COMMIT();

    for (int kt = 0; kt < NK; kt++) {
        CP_WAIT2();          // stage kt landed (kt+1, kt+2 may be in flight)
        __syncthreads();     // prev iter's MMAs done -> buffer (kt+3)%4 free

        if (kt + 3 < NK) load_stage((kt + 3) & 3, kt + 3);
        CP_COMMIT();         // unconditional: keeps group counting aligned

        const uint32_t stU = (kt & 3) * STAGE_B;

        #pragma unroll
        for (int ko = 0; ko < 2; ko++) {
            const uint32_t kb = stU + ko * 32;

            uint32_t Af[4][4];
            #pragma unroll
            for (int mt = 0; mt < 4; mt++)
                ldsm_x4(Af[mt][0], Af[mt][1], Af[mt][2], Af[mt][3],
                        aAddr + kb + mt * (16 * ROWB));

            uint32_t Bf[2][4];
            #pragma unroll
            for (int np = 0; np < 2; np++)
                ldsm_x4(Bf[np][0], Bf[np][1], Bf[np][2], Bf[np][3],
                        bAddr + kb + np * (16 * ROWB));

            #pragma unroll
            for (int mt = 0; mt < 4; mt++)
                #pragma unroll
                for (int nt = 0; nt < 4; nt++) {
                    const int np = nt >> 1, pr = (nt & 1) * 2;
                    mma_f16(acc[mt][nt],
                            Af[mt][0], Af[mt][1], Af[mt][2], Af[mt][3],
                            Bf[np][pr], Bf[np][pr + 1]);
                }
        }
    }

    const int c0 = (lane & 3) * 2;

    if constexpr (sizeof(OutT) == 4) {
        // fp32: direct float2 stores (4 lanes x 8B = full 32B sectors)
        #pragma unroll
        for (int mt = 0; mt < 4; mt++) {
            #pragma unroll
            for (int nt = 0; nt < 4; nt++) {
                int colL = wn + nt * 8 + c0;
                int col  = bn + colL;
                float b0v = biasS[colL];
                float b1v = biasS[colL + 1];
                int row0 = bm + wm + mt * 16 + g0;
                float2 v0 = make_float2(fmaf(acc[mt][nt][0], out_scale, b0v),
                                        fmaf(acc[mt][nt][1], out_scale, b1v));
                float2 v1 = make_float2(fmaf(acc[mt][nt][2], out_scale, b0v),
                                        fmaf(acc[mt][nt][3], out_scale, b1v));
                *(float2*)((float*)C + (size_t)row0 * N + col)       = v0;
                *(float2*)((float*)C + (size_t)(row0 + 8) * N + col) = v1;
            }
        }
    } else {
        // fp16: stage through smem (pitch 272B, conflict-free), then
        // 16B copy-out -> full-sector gmem stores (no read-modify-write).
        __syncthreads();     // all MMAs done; safe to reuse tile smem
        char* cbuf = tiles;  // 128 * 272 = 34816 <= NSTAGE*STAGE_B
        #pragma unroll
        for (int mt = 0; mt < 4; mt++) {
            #pragma unroll
            for (int nt = 0; nt < 4; nt++) {
                int colL = wn + nt * 8 + c0;
                float b0v = biasS[colL];
                float b1v = biasS[colL + 1];
                int r0 = wm + mt * 16 + g0;
                __half2 v0 = __floats2half2_rn(
                    fmaf(acc[mt][nt][0], out_scale, b0v),
                    fmaf(acc[mt][nt][1], out_scale, b1v));
                __half2 v1 = __floats2half2_rn(
                    fmaf(acc[mt][nt][2], out_scale, b0v),
                    fmaf(acc[mt][nt][3], out_scale, b1v));
                *(__half2*)(cbuf + r0 * CPITCH + colL * 2)       = v0;
                *(__half2*)(cbuf + (r0 + 8) * CPITCH + colL * 2) = v1;
            }
        }
        __syncthreads();
        // 128 rows x 256B = 2048 16B-chunks; 8 per thread.
        #pragma unroll
        for (int k = 0; k < 8; k++) {
            int c = tid + k * 256;
            int row = c >> 4;
            int off = (c & 15) * 16;
            uint4 v = *(uint4*)(cbuf + row * CPITCH + off);
            *(uint4*)((char*)C + ((size_t)(bm + row) * N + bn) * 2 + off) = v;
        }
    }
}

// ---------------------------------------------------------------------------
// IndRNN scan (scaled domain), __half2 vectorized, prefetch distance 2,
// SM-balanced grid: 296 blocks (2 per SM exactly), 56 channels per block.
//   O2[b,t,h2] = relu2(P2[b,t,h2] + u2[h2]*O2[b,t-1,h2])
// ---------------------------------------------------------------------------
#define H2 (HH / 2)        // 256 half2 channels per batch
#define SCAN_BLOCKS 296    // = 2 * 148 SMs: one balanced wave
#define SCAN_CHB 56        // ceil(BB*H2 / 293) -> 56 channels per block

__global__ __launch_bounds__(64)
void scan_relu_f16v2(const __half2* __restrict__ P,
                     const float* __restrict__ u,
                     __half2* __restrict__ O)
{
    int t = threadIdx.x;
    if (t >= SCAN_CHB) return;
    int idx = blockIdx.x * SCAN_CHB + t;   // 0 .. BB*H2-1
    if (idx >= BB * H2) return;
    int b  = idx / H2;
    int h2 = idx - b * H2;
    float u0 = u[h2 * 2];
    float u1 = u[h2 * 2 + 1];
    float hv0 = 0.0f, hv1 = 0.0f;
    const __half2* p = P + (size_t)b * TT * H2 + h2;
    __half2* o = O + (size_t)b * TT * H2 + h2;

    constexpr int U = 32;
    constexpr int NB = TT / U;   // 64 blocks

    __half2 x[U], y[U];
    #pragma unroll
    for (int i = 0; i < U; i++) x[i] = p[(size_t)i * H2];
    #pragma unroll
    for (int i = 0; i < U; i++) y[i] = p[(size_t)(U + i) * H2];

    #pragma unroll 1
    for (int blk = 0; blk < NB; blk++) {
        __half2 z[U];
        bool more2 = (blk + 2) < NB;
        const __half2* pz = p + (size_t)2 * U * H2;
        if (more2) {
            #pragma unroll
            for (int i = 0; i < U; i++) z[i] = pz[(size_t)i * H2];
        }
        #pragma unroll
        for (int i = 0; i < U; i++) {
            float2 f = __half22float2(x[i]);
            hv0 = fmaxf(fmaf(u0, hv0, f.x), 0.0f);
            hv1 = fmaxf(fmaf(u1, hv1, f.y), 0.0f);
            o[(size_t)i * H2] = __floats2half2_rn(hv0, hv1);
        }
        #pragma unroll
        for (int i = 0; i < U; i++) { x[i] = y[i]; y[i] = z[i]; }
        p += (size_t)U * H2;
        o += (size_t)U * H2;
    }
}

// ---------------------------------------------------------------------------
// Merged converter: x, W0, W1, fcW -> fp16 in one launch (weight conversion
// rides under the x-convert's DRAM stream instead of a separate launch).
// ---------------------------------------------------------------------------
__global__ void convert_all(const float* __restrict__ X,
                            const float* __restrict__ W0,
                            const float* __restrict__ W1,
                            const float* __restrict__ FW,
                            __half* __restrict__ x16,
                            __half* __restrict__ w0,
                            __half* __restrict__ w1,
                            __half* __restrict__ fw)
{
    constexpr int nx = MM * DIN;           // 16777216
    constexpr int n0 = HH * DIN;           // 65536
    constexpr int n1 = HH * HH;            // 262144
    constexpr int n2 = DOUT * HH;          // 65536
    int i = (blockIdx.x * blockDim.x + threadIdx.x) * 4;
    const float* src;
    __half* dst;
    int j;
    if (i < nx)                     { src = X;  dst = x16; j = i; }
    else if (i < nx + n0)           { src = W0; dst = w0;  j = i - nx; }
    else if (i < nx + n0 + n1)      { src = W1; dst = w1;  j = i - nx - n0; }
    else if (i < nx + n0 + n1 + n2) { src = FW; dst = fw;  j = i - nx - n0 - n1; }
    else return;
    float4 v = *(const float4*)(src + j);
    __half2 h0 = __floats2half2_rn(v.x, v.y);
    __half2 h1 = __floats2half2_rn(v.z, v.w);
    *(uint2*)(dst + j) = make_uint2(*(uint32_t*)&h0, *(uint32_t*)&h1);
}

extern "C" void kernel_launch(void* const* d_in, const int* in_sizes, int n_in,
                              void* d_out, int out_size)
{
    const float* x    = (const float*)d_in[0];
    const float* W0   = (const float*)d_in[1];
    const float* bl0  = (const float*)d_in[2];
    const float* u0   = (const float*)d_in[3];
    const float* bb0  = (const float*)d_in[4];
    const float* W1   = (const float*)d_in[5];
    const float* bl1  = (const float*)d_in[6];
    const float* u1   = (const float*)d_in[7];
    const float* bb1  = (const float*)d_in[8];
    const float* fcW  = (const float*)d_in[9];
    const float* fcb  = (const float*)d_in[10];
    float* out = (float*)d_out;

    __half *proj, *act, *x16, *w0, *w1, *fw;
    cudaGetSymbolAddress((void**)&proj, g_proj);
    cudaGetSymbolAddress((void**)&act,  g_act);
    cudaGetSymbolAddress((void**)&x16,  g_x16);
    cudaGetSymbolAddress((void**)&w0,   g_w0);
    cudaGetSymbolAddress((void**)&w1,   g_w1);
    cudaGetSymbolAddress((void**)&fw,   g_fw);

    cudaFuncSetAttribute(gemm_f16<__half>,
                         cudaFuncAttributeMaxDynamicSharedMemorySize,
                         SMEM_GEMM);
    cudaFuncSetAttribute(gemm_f16<float>,
                         cudaFuncAttributeMaxDynamicSharedMemorySize,
                         SMEM_GEMM);

    // x + all weights -> fp16 in one launch
    {
        int total = MM * DIN + HH * DIN + HH * HH + DOUT * HH;
        convert_all<<<(total / 4 + 255) / 256, 256>>>(x, W0, W1, fcW,
                                                      x16, w0, w1, fw);
    }

    // Layer 0 in the x2^-4 domain:
    // GEMM0: proj = (x@W0^T + bl0 + bb0) * 2^-4   (fp16, staged epilogue)
    {
        dim3 grid(HH / 128, MM / 128);
        gemm_f16<__half><<<grid, 256, SMEM_GEMM>>>(x16, w0, bl0, bb0, proj,
                                                   MM, HH, DIN,
                                                   0.0625f, 0.0625f);
    }
    // scan0: act = h1 * 2^-4 (relu is positively homogeneous)
    scan_relu_f16v2<<<SCAN_BLOCKS, 64>>>((const __half2*)proj, u0,
                                         (__half2*)act);

    // Layer 1 in the x2^-8 domain:
    // GEMM1: proj = (h1*2^-4)@W1^T * 2^-4 + (bl1+bb1)*2^-8 = proj1 * 2^-8
    {
        dim3 grid(HH / 128, MM / 128);
        gemm_f16<__half><<<grid, 256, SMEM_GEMM>>>(act, w1, bl1, bb1, proj,
                                                   MM, HH, HH,
                                                   0.0625f, 0.00390625f);
    }
    // scan1: act = h2 * 2^-8
    scan_relu_f16v2<<<SCAN_BLOCKS, 64>>>((const __half2*)proj, u1,
                                         (__half2*)act);

    // GEMM2: out = (h2*2^-8)@fcW^T * 256 + fcb   (fp32 out, direct epilogue)
    {
        dim3 grid(DOUT / 128, MM / 128);
        gemm_f16<float><<<grid, 256, SMEM_GEMM>>>(act, fw, fcb, nullptr, out,
                                                  MM, DOUT, HH,
                                                  256.0f, 1.0f);
    }
}